// round 8
// baseline (speedup 1.0000x reference)
#include <cuda_runtime.h>
#include <math.h>

// Problem constants
#define BB 4
#define TT 4096
#define CC 1024
#define HH 64
#define BQ 64
#define BKT 64
#define NT (TT / BQ)
#define CHUNK 8
#define MAXSPL 8

typedef unsigned long long u64;

// ---- packed fp32x2 helpers (ptxas never emits FFMA2 from C++) ----
__device__ __forceinline__ void fma2(u64& d, u64 a, u64 b) {
    asm("fma.rn.f32x2 %0, %1, %2, %0;" : "+l"(d) : "l"(a), "l"(b));
}
__device__ __forceinline__ void mul2(u64& d, u64 a, u64 b) {
    asm("mul.rn.f32x2 %0, %1, %2;" : "=l"(d) : "l"(a), "l"(b));
}
__device__ __forceinline__ u64 pack2(float lo, float hi) {
    u64 d; asm("mov.b64 %0, {%1, %2};" : "=l"(d) : "f"(lo), "f"(hi)); return d;
}
__device__ __forceinline__ float2 unpack2(u64 v) {
    float2 r; asm("mov.b64 {%0, %1}, %2;" : "=f"(r.x), "=f"(r.y) : "l"(v)); return r;
}

// Scratch (no cudaMalloc allowed)
__device__ float g_q[BB * TT * HH];
__device__ float g_k[BB * TT * HH];
__device__ float g_v[BB * TT * HH];
__device__ float g_opart[BB * NT * MAXSPL * BQ * HH];
__device__ float g_mpart[BB * NT * MAXSPL * BQ];
__device__ float g_lpart[BB * NT * MAXSPL * BQ];

// ---------------------------------------------------------------------------
// Projection GEMM via FFMA2: out[16384,64] = x[16384,1024] @ W[1024,64]
// A stored duplicated in smem so the scalar operand is a free (a,a) pair;
// B pairs (c,c+1) are contiguous in row-major W. grid (128, 3), block 256.
// ---------------------------------------------------------------------------
__global__ __launch_bounds__(256) void proj_kernel(
    const float* __restrict__ x,
    const float* __restrict__ Wk,
    const float* __restrict__ Wq,
    const float* __restrict__ Wv)
{
    __shared__ __align__(16) float As2[128 * 68];  // dup format: [row][2k..2k+1]=(a,a)
    __shared__ __align__(16) float Bs[32 * 64];

    const float* W;
    float* out;
    if (blockIdx.y == 0)      { W = Wq; out = g_q; }
    else if (blockIdx.y == 1) { W = Wk; out = g_k; }
    else                      { W = Wv; out = g_v; }

    const int rowBase = blockIdx.x * 128;
    const int tid = threadIdx.x;
    const int ty = tid >> 4;
    const int tx = tid & 15;

    u64 acc[8][2];
#pragma unroll
    for (int i = 0; i < 8; i++) { acc[i][0] = 0ULL; acc[i][1] = 0ULL; }

    const int lr  = tid >> 3;
    const int lf4 = (tid & 7) * 4;
    const int lkk = tid >> 4;
    const int lh4 = (tid & 15) * 4;

    for (int k0 = 0; k0 < CC; k0 += 32) {
#pragma unroll
        for (int it = 0; it < 4; it++) {
            int row = lr + it * 32;
            float4 v = *(const float4*)(x + (size_t)(rowBase + row) * CC + k0 + lf4);
            ulonglong2* dst = (ulonglong2*)&As2[row * 68 + 2 * lf4];
            dst[0] = make_ulonglong2(pack2(v.x, v.x), pack2(v.y, v.y));
            dst[1] = make_ulonglong2(pack2(v.z, v.z), pack2(v.w, v.w));
        }
#pragma unroll
        for (int it = 0; it < 2; it++) {
            *(float4*)(&Bs[(lkk + it * 16) * 64 + lh4]) =
                *(const float4*)(W + (size_t)(k0 + lkk + it * 16) * HH + lh4);
        }
        __syncthreads();

#pragma unroll 4
        for (int kk = 0; kk < 32; kk++) {
            ulonglong2 b = *(const ulonglong2*)(&Bs[kk * 64 + tx * 4]);
#pragma unroll
            for (int i = 0; i < 8; i++) {
                u64 a = *(const u64*)(&As2[(ty * 8 + i) * 68 + 2 * kk]);
                fma2(acc[i][0], a, b.x);
                fma2(acc[i][1], a, b.y);
            }
        }
        __syncthreads();
    }

#pragma unroll
    for (int i = 0; i < 8; i++) {
        float2 c01 = unpack2(acc[i][0]);
        float2 c23 = unpack2(acc[i][1]);
        *(float4*)(out + (size_t)(rowBase + ty * 8 + i) * HH + tx * 4) =
            make_float4(c01.x, c01.y, c23.x, c23.y);
    }
}

// ---------------------------------------------------------------------------
// Split-KV flash attention, FFMA2 everywhere.
// S-phase: h-packed (lo=even h, hi=odd h), operands contiguous.
// O-phase: c-packed; P stored duplicated in smem (Ps2 aliases Qs+Ks,
// Q reloaded each kt). Static smem = 48 KB. grid (NT, MAXSPL, BB).
// ---------------------------------------------------------------------------
__global__ __launch_bounds__(256, 2) void attn_kernel()
{
    __shared__ __align__(16) float sm[3 * BQ * HH];  // 48 KB
    float* Qs  = sm;              // 16 KB
    float* Ks  = sm + 4096;       // 16 KB
    float* Vs  = sm + 8192;       // 16 KB
    float* Ps2 = sm;              // 32 KB, aliases Qs+Ks (sync-guarded)

    const int qt    = blockIdx.x;
    const int split = blockIdx.y;
    const int b     = blockIdx.z;
    const int nspl  = (qt + CHUNK) / CHUNK;
    if (split >= nspl) return;

    const int ktBeg = split * CHUNK;
    const int ktEnd = min(ktBeg + CHUNK, qt + 1);
    const int qbase = qt * BQ;

    const float* qg = g_q + ((size_t)b * TT + qbase) * HH;
    const float* kg = g_k + (size_t)b * TT * HH;
    const float* vg = g_v + (size_t)b * TT * HH;

    const int tid = threadIdx.x;
    const int ty = tid >> 4;
    const int tx = tid & 15;

    float m_i[4], l_i[4];
    u64 o2[4][2];
#pragma unroll
    for (int i = 0; i < 4; i++) {
        m_i[i] = -3.0e38f;
        l_i[i] = 0.0f;
        o2[i][0] = 0ULL;
        o2[i][1] = 0ULL;
    }

    const float scale = 0.03125f;  // 1024^-0.5

    for (int kt = ktBeg; kt < ktEnd; kt++) {
        const int kbase = kt * BKT;

        __syncthreads();  // previous O-phase reads of Ps2/Vs complete
        // Load Q (reloaded every kt since Ps2 overwrote it), K, V
#pragma unroll
        for (int it = 0; it < 4; it++) {
            int idx = tid + it * 256;
            int row = idx >> 4;
            int h4  = (idx & 15) * 4;
            int swz = (h4 + 4 * row) & 63;
            float4 qv = *(const float4*)(qg + row * HH + h4);
            *(float4*)(&Qs[row * HH + swz]) = qv;
            float4 kv = *(const float4*)(kg + (size_t)(kbase + row) * HH + h4);
            *(float4*)(&Ks[row * HH + swz]) = kv;
            float4 vv = *(const float4*)(vg + (size_t)(kbase + row) * HH + h4);
            *(float4*)(&Vs[row * HH + h4]) = vv;
        }
        __syncthreads();

        // ---- S = Q K^T, h-packed FFMA2 ----
        u64 s2[4][4];
#pragma unroll
        for (int i = 0; i < 4; i++)
#pragma unroll
            for (int j = 0; j < 4; j++) s2[i][j] = 0ULL;

#pragma unroll 2
        for (int h = 0; h < HH; h += 4) {
            ulonglong2 q2[4], k2[4];
#pragma unroll
            for (int i = 0; i < 4; i++) {
                int r = ty * 4 + i;
                q2[i] = *(const ulonglong2*)(&Qs[r * HH + ((h + 4 * r) & 63)]);
            }
#pragma unroll
            for (int j = 0; j < 4; j++) {
                int c = tx * 4 + j;
                k2[j] = *(const ulonglong2*)(&Ks[c * HH + ((h + 4 * c) & 63)]);
            }
#pragma unroll
            for (int i = 0; i < 4; i++)
#pragma unroll
                for (int j = 0; j < 4; j++) {
                    fma2(s2[i][j], q2[i].x, k2[j].x);
                    fma2(s2[i][j], q2[i].y, k2[j].y);
                }
        }

        // ---- mask + online softmax ----
        const bool diag = (kt == qt);
        float p[4][4];
#pragma unroll
        for (int i = 0; i < 4; i++) {
            const int row = qbase + ty * 4 + i;
            float sv[4];
            float mx = -3.0e38f;
#pragma unroll
            for (int j = 0; j < 4; j++) {
                float2 ss = unpack2(s2[i][j]);
                float v = (ss.x + ss.y) * scale;
                if (diag && (kbase + tx * 4 + j) > row) v = -3.0e38f;
                sv[j] = v;
                mx = fmaxf(mx, v);
            }
#pragma unroll
            for (int off = 8; off; off >>= 1)
                mx = fmaxf(mx, __shfl_xor_sync(0xffffffffu, mx, off));
            const float mnew = fmaxf(m_i[i], mx);
            const float corr = __expf(m_i[i] - mnew);
            float rsum = 0.0f;
#pragma unroll
            for (int j = 0; j < 4; j++) {
                float pv = __expf(sv[j] - mnew);
                p[i][j] = pv;
                rsum += pv;
            }
#pragma unroll
            for (int off = 8; off; off >>= 1)
                rsum += __shfl_xor_sync(0xffffffffu, rsum, off);
            l_i[i] = l_i[i] * corr + rsum;
            m_i[i] = mnew;
            u64 corrd = pack2(corr, corr);
            mul2(o2[i][0], o2[i][0], corrd);
            mul2(o2[i][1], o2[i][1], corrd);
        }

        __syncthreads();  // all Qs/Ks reads done before Ps2 overwrites them
        // Write P duplicated: Ps2[row][2j..2j+1] = (p_j, p_j)
#pragma unroll
        for (int i = 0; i < 4; i++) {
            int row = ty * 4 + i;
            ulonglong2* dst = (ulonglong2*)&Ps2[row * 128 + 8 * tx];
            dst[0] = make_ulonglong2(pack2(p[i][0], p[i][0]), pack2(p[i][1], p[i][1]));
            dst[1] = make_ulonglong2(pack2(p[i][2], p[i][2]), pack2(p[i][3], p[i][3]));
        }
        __syncthreads();

        // ---- O += P V, c-packed FFMA2 (dup P from smem, V pairs contiguous) ----
#pragma unroll 2
        for (int j4 = 0; j4 < BKT / 4; j4++) {
            ulonglong2 v0 = *(const ulonglong2*)(&Vs[(4 * j4 + 0) * HH + tx * 4]);
            ulonglong2 v1 = *(const ulonglong2*)(&Vs[(4 * j4 + 1) * HH + tx * 4]);
            ulonglong2 v2 = *(const ulonglong2*)(&Vs[(4 * j4 + 2) * HH + tx * 4]);
            ulonglong2 v3 = *(const ulonglong2*)(&Vs[(4 * j4 + 3) * HH + tx * 4]);
#pragma unroll
            for (int i = 0; i < 4; i++) {
                const float* pr = &Ps2[(ty * 4 + i) * 128 + 8 * j4];
                ulonglong2 pa = *(const ulonglong2*)(pr);
                ulonglong2 pb = *(const ulonglong2*)(pr + 4);
                fma2(o2[i][0], pa.x, v0.x);
                fma2(o2[i][1], pa.x, v0.y);
                fma2(o2[i][0], pa.y, v1.x);
                fma2(o2[i][1], pa.y, v1.y);
                fma2(o2[i][0], pb.x, v2.x);
                fma2(o2[i][1], pb.x, v2.y);
                fma2(o2[i][0], pb.y, v3.x);
                fma2(o2[i][1], pb.y, v3.y);
            }
        }
    }

    // Epilogue: write unnormalized partial + row stats
    const size_t pidx = (size_t)((b * NT + qt) * MAXSPL + split);
    float* op = g_opart + pidx * (BQ * HH);
#pragma unroll
    for (int i = 0; i < 4; i++) {
        float2 c01 = unpack2(o2[i][0]);
        float2 c23 = unpack2(o2[i][1]);
        *(float4*)(op + (ty * 4 + i) * HH + tx * 4) =
            make_float4(c01.x, c01.y, c23.x, c23.y);
        if (tx == 0) {
            g_mpart[pidx * BQ + ty * 4 + i] = m_i[i];
            g_lpart[pidx * BQ + ty * 4 + i] = l_i[i];
        }
    }
}

// ---------------------------------------------------------------------------
// Merge: combine <= MAXSPL partials per row.
// ---------------------------------------------------------------------------
__global__ __launch_bounds__(256) void merge_kernel(float* __restrict__ out)
{
    const int gid = blockIdx.x * 256 + threadIdx.x;
    const int row = gid >> 4;
    const int cx  = (gid & 15) * 4;
    const int b  = row >> 12;
    const int t  = row & (TT - 1);
    const int qt = t >> 6;
    const int r  = t & (BQ - 1);
    const int ns = (qt + CHUNK) / CHUNK;

    const size_t mlBase = (size_t)(b * NT + qt) * MAXSPL * BQ + r;

    float M = -3.0e38f;
    for (int s = 0; s < ns; s++)
        M = fmaxf(M, g_mpart[mlBase + (size_t)s * BQ]);

    float L = 0.0f;
    float a0 = 0.0f, a1 = 0.0f, a2 = 0.0f, a3 = 0.0f;
    for (int s = 0; s < ns; s++) {
        const float w = __expf(g_mpart[mlBase + (size_t)s * BQ] - M);
        L += w * g_lpart[mlBase + (size_t)s * BQ];
        const float* op = g_opart
            + (size_t)((b * NT + qt) * MAXSPL + s) * (BQ * HH) + r * HH + cx;
        float4 v = *(const float4*)op;
        a0 = fmaf(w, v.x, a0);
        a1 = fmaf(w, v.y, a1);
        a2 = fmaf(w, v.z, a2);
        a3 = fmaf(w, v.w, a3);
    }
    const float inv = 1.0f / L;
    *(float4*)(out + (size_t)row * HH + cx) =
        make_float4(a0 * inv, a1 * inv, a2 * inv, a3 * inv);
}

// ---------------------------------------------------------------------------
extern "C" void kernel_launch(void* const* d_in, const int* in_sizes, int n_in,
                              void* d_out, int out_size)
{
    const float* x  = (const float*)d_in[0];
    const float* Wk = (const float*)d_in[1];
    const float* Wq = (const float*)d_in[2];
    const float* Wv = (const float*)d_in[3];
    float* out = (float*)d_out;

    dim3 gProj((BB * TT) / 128, 3);
    proj_kernel<<<gProj, 256>>>(x, Wk, Wq, Wv);

    dim3 gAttn(NT, MAXSPL, BB);
    attn_kernel<<<gAttn, 256>>>();

    merge_kernel<<<(BB * TT * 16) / 256, 256>>>(out);
}

// round 9
// speedup vs baseline: 1.0013x; 1.0013x over previous
#include <cuda_runtime.h>
#include <math.h>

// Problem constants
#define BB 4
#define TT 4096
#define CC 1024
#define HH 64
#define BQ 64
#define BKT 64
#define NT (TT / BQ)
#define CHUNK 8
#define MAXSPL 8

typedef unsigned long long u64;

// ---- packed fp32x2 helpers (ptxas never emits FFMA2 from C++) ----
__device__ __forceinline__ void fma2(u64& d, u64 a, u64 b) {
    asm("fma.rn.f32x2 %0, %1, %2, %0;" : "+l"(d) : "l"(a), "l"(b));
}
__device__ __forceinline__ void mul2(u64& d, u64 a, u64 b) {
    asm("mul.rn.f32x2 %0, %1, %2;" : "=l"(d) : "l"(a), "l"(b));
}
__device__ __forceinline__ u64 pack2(float lo, float hi) {
    u64 d; asm("mov.b64 %0, {%1, %2};" : "=l"(d) : "f"(lo), "f"(hi)); return d;
}
__device__ __forceinline__ float2 unpack2(u64 v) {
    float2 r; asm("mov.b64 {%0, %1}, %2;" : "=f"(r.x), "=f"(r.y) : "l"(v)); return r;
}

// Scratch (no cudaMalloc allowed)
__device__ float g_q[BB * TT * HH];
__device__ float g_k[BB * TT * HH];
__device__ float g_v[BB * TT * HH];
__device__ float g_opart[BB * NT * MAXSPL * BQ * HH];
__device__ float g_mpart[BB * NT * MAXSPL * BQ];
__device__ float g_lpart[BB * NT * MAXSPL * BQ];

// ---------------------------------------------------------------------------
// Projection GEMM via FFMA2: out[16384,64] = x[16384,1024] @ W[1024,64]
// A stored duplicated in smem so the scalar operand is a free (a,a) pair;
// B pairs (c,c+1) are contiguous in row-major W. grid (128, 3), block 256.
// ---------------------------------------------------------------------------
__global__ __launch_bounds__(256) void proj_kernel(
    const float* __restrict__ x,
    const float* __restrict__ Wk,
    const float* __restrict__ Wq,
    const float* __restrict__ Wv)
{
    __shared__ __align__(16) float As2[128 * 68];  // dup format: [row][2k..2k+1]=(a,a)
    __shared__ __align__(16) float Bs[32 * 64];

    const float* W;
    float* out;
    if (blockIdx.y == 0)      { W = Wq; out = g_q; }
    else if (blockIdx.y == 1) { W = Wk; out = g_k; }
    else                      { W = Wv; out = g_v; }

    const int rowBase = blockIdx.x * 128;
    const int tid = threadIdx.x;
    const int ty = tid >> 4;
    const int tx = tid & 15;

    u64 acc[8][2];
#pragma unroll
    for (int i = 0; i < 8; i++) { acc[i][0] = 0ULL; acc[i][1] = 0ULL; }

    const int lr  = tid >> 3;
    const int lf4 = (tid & 7) * 4;
    const int lkk = tid >> 4;
    const int lh4 = (tid & 15) * 4;

    for (int k0 = 0; k0 < CC; k0 += 32) {
#pragma unroll
        for (int it = 0; it < 4; it++) {
            int row = lr + it * 32;
            float4 v = *(const float4*)(x + (size_t)(rowBase + row) * CC + k0 + lf4);
            ulonglong2* dst = (ulonglong2*)&As2[row * 68 + 2 * lf4];
            dst[0] = make_ulonglong2(pack2(v.x, v.x), pack2(v.y, v.y));
            dst[1] = make_ulonglong2(pack2(v.z, v.z), pack2(v.w, v.w));
        }
#pragma unroll
        for (int it = 0; it < 2; it++) {
            *(float4*)(&Bs[(lkk + it * 16) * 64 + lh4]) =
                *(const float4*)(W + (size_t)(k0 + lkk + it * 16) * HH + lh4);
        }
        __syncthreads();

#pragma unroll 4
        for (int kk = 0; kk < 32; kk++) {
            ulonglong2 b = *(const ulonglong2*)(&Bs[kk * 64 + tx * 4]);
#pragma unroll
            for (int i = 0; i < 8; i++) {
                u64 a = *(const u64*)(&As2[(ty * 8 + i) * 68 + 2 * kk]);
                fma2(acc[i][0], a, b.x);
                fma2(acc[i][1], a, b.y);
            }
        }
        __syncthreads();
    }

#pragma unroll
    for (int i = 0; i < 8; i++) {
        float2 c01 = unpack2(acc[i][0]);
        float2 c23 = unpack2(acc[i][1]);
        *(float4*)(out + (size_t)(rowBase + ty * 8 + i) * HH + tx * 4) =
            make_float4(c01.x, c01.y, c23.x, c23.y);
    }
}

// ---------------------------------------------------------------------------
// Split-KV flash attention, FFMA2 everywhere.
// S-phase: h-packed (lo=even h, hi=odd h), operands contiguous.
// O-phase: c-packed; P stored duplicated in smem (Ps2 aliases Qs+Ks,
// Q reloaded each kt). Static smem = 48 KB. grid (NT, MAXSPL, BB).
// ---------------------------------------------------------------------------
__global__ __launch_bounds__(256, 2) void attn_kernel()
{
    __shared__ __align__(16) float sm[3 * BQ * HH];  // 48 KB
    float* Qs  = sm;              // 16 KB
    float* Ks  = sm + 4096;       // 16 KB
    float* Vs  = sm + 8192;       // 16 KB
    float* Ps2 = sm;              // 32 KB, aliases Qs+Ks (sync-guarded)

    const int qt    = blockIdx.x;
    const int split = blockIdx.y;
    const int b     = blockIdx.z;
    const int nspl  = (qt + CHUNK) / CHUNK;
    if (split >= nspl) return;

    const int ktBeg = split * CHUNK;
    const int ktEnd = min(ktBeg + CHUNK, qt + 1);
    const int qbase = qt * BQ;

    const float* qg = g_q + ((size_t)b * TT + qbase) * HH;
    const float* kg = g_k + (size_t)b * TT * HH;
    const float* vg = g_v + (size_t)b * TT * HH;

    const int tid = threadIdx.x;
    const int ty = tid >> 4;
    const int tx = tid & 15;

    float m_i[4], l_i[4];
    u64 o2[4][2];
#pragma unroll
    for (int i = 0; i < 4; i++) {
        m_i[i] = -3.0e38f;
        l_i[i] = 0.0f;
        o2[i][0] = 0ULL;
        o2[i][1] = 0ULL;
    }

    const float scale = 0.03125f;  // 1024^-0.5

    for (int kt = ktBeg; kt < ktEnd; kt++) {
        const int kbase = kt * BKT;

        __syncthreads();  // previous O-phase reads of Ps2/Vs complete
        // Load Q (reloaded every kt since Ps2 overwrote it), K, V
#pragma unroll
        for (int it = 0; it < 4; it++) {
            int idx = tid + it * 256;
            int row = idx >> 4;
            int h4  = (idx & 15) * 4;
            int swz = (h4 + 4 * row) & 63;
            float4 qv = *(const float4*)(qg + row * HH + h4);
            *(float4*)(&Qs[row * HH + swz]) = qv;
            float4 kv = *(const float4*)(kg + (size_t)(kbase + row) * HH + h4);
            *(float4*)(&Ks[row * HH + swz]) = kv;
            float4 vv = *(const float4*)(vg + (size_t)(kbase + row) * HH + h4);
            *(float4*)(&Vs[row * HH + h4]) = vv;
        }
        __syncthreads();

        // ---- S = Q K^T, h-packed FFMA2 ----
        u64 s2[4][4];
#pragma unroll
        for (int i = 0; i < 4; i++)
#pragma unroll
            for (int j = 0; j < 4; j++) s2[i][j] = 0ULL;

#pragma unroll 2
        for (int h = 0; h < HH; h += 4) {
            ulonglong2 q2[4], k2[4];
#pragma unroll
            for (int i = 0; i < 4; i++) {
                int r = ty * 4 + i;
                q2[i] = *(const ulonglong2*)(&Qs[r * HH + ((h + 4 * r) & 63)]);
            }
#pragma unroll
            for (int j = 0; j < 4; j++) {
                int c = tx * 4 + j;
                k2[j] = *(const ulonglong2*)(&Ks[c * HH + ((h + 4 * c) & 63)]);
            }
#pragma unroll
            for (int i = 0; i < 4; i++)
#pragma unroll
                for (int j = 0; j < 4; j++) {
                    fma2(s2[i][j], q2[i].x, k2[j].x);
                    fma2(s2[i][j], q2[i].y, k2[j].y);
                }
        }

        // ---- mask + online softmax ----
        const bool diag = (kt == qt);
        float p[4][4];
#pragma unroll
        for (int i = 0; i < 4; i++) {
            const int row = qbase + ty * 4 + i;
            float sv[4];
            float mx = -3.0e38f;
#pragma unroll
            for (int j = 0; j < 4; j++) {
                float2 ss = unpack2(s2[i][j]);
                float v = (ss.x + ss.y) * scale;
                if (diag && (kbase + tx * 4 + j) > row) v = -3.0e38f;
                sv[j] = v;
                mx = fmaxf(mx, v);
            }
#pragma unroll
            for (int off = 8; off; off >>= 1)
                mx = fmaxf(mx, __shfl_xor_sync(0xffffffffu, mx, off));
            const float mnew = fmaxf(m_i[i], mx);
            const float corr = __expf(m_i[i] - mnew);
            float rsum = 0.0f;
#pragma unroll
            for (int j = 0; j < 4; j++) {
                float pv = __expf(sv[j] - mnew);
                p[i][j] = pv;
                rsum += pv;
            }
#pragma unroll
            for (int off = 8; off; off >>= 1)
                rsum += __shfl_xor_sync(0xffffffffu, rsum, off);
            l_i[i] = l_i[i] * corr + rsum;
            m_i[i] = mnew;
            u64 corrd = pack2(corr, corr);
            mul2(o2[i][0], o2[i][0], corrd);
            mul2(o2[i][1], o2[i][1], corrd);
        }

        __syncthreads();  // all Qs/Ks reads done before Ps2 overwrites them
        // Write P duplicated: Ps2[row][2j..2j+1] = (p_j, p_j)
#pragma unroll
        for (int i = 0; i < 4; i++) {
            int row = ty * 4 + i;
            ulonglong2* dst = (ulonglong2*)&Ps2[row * 128 + 8 * tx];
            dst[0] = make_ulonglong2(pack2(p[i][0], p[i][0]), pack2(p[i][1], p[i][1]));
            dst[1] = make_ulonglong2(pack2(p[i][2], p[i][2]), pack2(p[i][3], p[i][3]));
        }
        __syncthreads();

        // ---- O += P V, c-packed FFMA2 (dup P from smem, V pairs contiguous) ----
#pragma unroll 2
        for (int j4 = 0; j4 < BKT / 4; j4++) {
            ulonglong2 v0 = *(const ulonglong2*)(&Vs[(4 * j4 + 0) * HH + tx * 4]);
            ulonglong2 v1 = *(const ulonglong2*)(&Vs[(4 * j4 + 1) * HH + tx * 4]);
            ulonglong2 v2 = *(const ulonglong2*)(&Vs[(4 * j4 + 2) * HH + tx * 4]);
            ulonglong2 v3 = *(const ulonglong2*)(&Vs[(4 * j4 + 3) * HH + tx * 4]);
#pragma unroll
            for (int i = 0; i < 4; i++) {
                const float* pr = &Ps2[(ty * 4 + i) * 128 + 8 * j4];
                ulonglong2 pa = *(const ulonglong2*)(pr);
                ulonglong2 pb = *(const ulonglong2*)(pr + 4);
                fma2(o2[i][0], pa.x, v0.x);
                fma2(o2[i][1], pa.x, v0.y);
                fma2(o2[i][0], pa.y, v1.x);
                fma2(o2[i][1], pa.y, v1.y);
                fma2(o2[i][0], pb.x, v2.x);
                fma2(o2[i][1], pb.x, v2.y);
                fma2(o2[i][0], pb.y, v3.x);
                fma2(o2[i][1], pb.y, v3.y);
            }
        }
    }

    // Epilogue: write unnormalized partial + row stats
    const size_t pidx = (size_t)((b * NT + qt) * MAXSPL + split);
    float* op = g_opart + pidx * (BQ * HH);
#pragma unroll
    for (int i = 0; i < 4; i++) {
        float2 c01 = unpack2(o2[i][0]);
        float2 c23 = unpack2(o2[i][1]);
        *(float4*)(op + (ty * 4 + i) * HH + tx * 4) =
            make_float4(c01.x, c01.y, c23.x, c23.y);
        if (tx == 0) {
            g_mpart[pidx * BQ + ty * 4 + i] = m_i[i];
            g_lpart[pidx * BQ + ty * 4 + i] = l_i[i];
        }
    }
}

// ---------------------------------------------------------------------------
// Merge: combine <= MAXSPL partials per row.
// ---------------------------------------------------------------------------
__global__ __launch_bounds__(256) void merge_kernel(float* __restrict__ out)
{
    const int gid = blockIdx.x * 256 + threadIdx.x;
    const int row = gid >> 4;
    const int cx  = (gid & 15) * 4;
    const int b  = row >> 12;
    const int t  = row & (TT - 1);
    const int qt = t >> 6;
    const int r  = t & (BQ - 1);
    const int ns = (qt + CHUNK) / CHUNK;

    const size_t mlBase = (size_t)(b * NT + qt) * MAXSPL * BQ + r;

    float M = -3.0e38f;
    for (int s = 0; s < ns; s++)
        M = fmaxf(M, g_mpart[mlBase + (size_t)s * BQ]);

    float L = 0.0f;
    float a0 = 0.0f, a1 = 0.0f, a2 = 0.0f, a3 = 0.0f;
    for (int s = 0; s < ns; s++) {
        const float w = __expf(g_mpart[mlBase + (size_t)s * BQ] - M);
        L += w * g_lpart[mlBase + (size_t)s * BQ];
        const float* op = g_opart
            + (size_t)((b * NT + qt) * MAXSPL + s) * (BQ * HH) + r * HH + cx;
        float4 v = *(const float4*)op;
        a0 = fmaf(w, v.x, a0);
        a1 = fmaf(w, v.y, a1);
        a2 = fmaf(w, v.z, a2);
        a3 = fmaf(w, v.w, a3);
    }
    const float inv = 1.0f / L;
    *(float4*)(out + (size_t)row * HH + cx) =
        make_float4(a0 * inv, a1 * inv, a2 * inv, a3 * inv);
}

// ---------------------------------------------------------------------------
extern "C" void kernel_launch(void* const* d_in, const int* in_sizes, int n_in,
                              void* d_out, int out_size)
{
    const float* x  = (const float*)d_in[0];
    const float* Wk = (const float*)d_in[1];
    const float* Wq = (const float*)d_in[2];
    const float* Wv = (const float*)d_in[3];
    float* out = (float*)d_out;

    dim3 gProj((BB * TT) / 128, 3);
    proj_kernel<<<gProj, 256>>>(x, Wk, Wq, Wv);

    dim3 gAttn(NT, MAXSPL, BB);
    attn_kernel<<<gAttn, 256>>>();

    merge_kernel<<<(BB * TT * 16) / 256, 256>>>(out);
}

// round 11
// speedup vs baseline: 1.2715x; 1.2698x over previous
#include <cuda_runtime.h>
#include <math.h>
#include <stdint.h>

// Problem constants
#define BB 4
#define TT 4096
#define CC 1024
#define HH 64
#define BQ 64
#define BKT 64
#define NT (TT / BQ)
#define CHUNK 8
#define MAXSPL 8

// Scratch (no cudaMalloc allowed)
__device__ float g_q[BB * TT * HH];
__device__ float g_k[BB * TT * HH];
__device__ float g_v[BB * TT * HH];
__device__ float g_opart[BB * NT * MAXSPL * BQ * HH];
__device__ float g_mpart[BB * NT * MAXSPL * BQ];
__device__ float g_lpart[BB * NT * MAXSPL * BQ];

// ---- base-ISA tensor core: mma.sync m16n8k8 tf32 (sm_80+, no 'a' gating) ----
__device__ __forceinline__ void mma_tf32(float* d, const uint32_t* a,
                                         const uint32_t* b) {
    asm volatile(
        "mma.sync.aligned.m16n8k8.row.col.f32.tf32.tf32.f32 "
        "{%0,%1,%2,%3}, {%4,%5,%6,%7}, {%8,%9}, {%0,%1,%2,%3};"
        : "+f"(d[0]), "+f"(d[1]), "+f"(d[2]), "+f"(d[3])
        : "r"(a[0]), "r"(a[1]), "r"(a[2]), "r"(a[3]), "r"(b[0]), "r"(b[1]));
}
__device__ __forceinline__ float to_tf32(float f) {
    float o;
    asm("cvt.rna.tf32.f32 %0, %1;" : "=f"(o) : "f"(f));
    return o;
}
__device__ __forceinline__ float4 tf32x4(float4 v) {
    v.x = to_tf32(v.x); v.y = to_tf32(v.y);
    v.z = to_tf32(v.z); v.w = to_tf32(v.w);
    return v;
}

// ===========================================================================
// Projection GEMM on HMMA (tf32): q,k,v[16384,64] = x[16384,1024] @ W[1024,64]
// grid = 128 CTAs x 384 threads (12 warps). warp w: m = w>>2 (which matrix),
// s = w&3 (32-row slice). Each warp: 32x64 output = 2x8 m16n8k8 fragments.
// K loop: 32 chunks of KC=32 (4 k8-steps each), x/W reg-prefetch double-buffer.
// Smem padded strides are conflict-free for the fragment gather patterns.
// ===========================================================================
#define KC 32
__global__ __launch_bounds__(384) void proj_mma_kernel(
    const float* __restrict__ x,
    const float* __restrict__ Wk,
    const float* __restrict__ Wq,
    const float* __restrict__ Wv)
{
    __shared__ float As[128][36];        // x tile [128][KC], stride 36
    __shared__ float Bs[3][KC][72];      // W tiles [KC][64], stride 72

    const int tid  = threadIdx.x;
    const int w    = tid >> 5;
    const int lane = tid & 31;
    const int g    = lane >> 2;   // groupID 0..7
    const int t4   = lane & 3;    // thread-in-group 0..3
    const int s    = w & 3;       // row slice
    const int m    = w >> 2;      // matrix 0=q 1=k 2=v

    const int rowBase = blockIdx.x * 128;

    float d[2][8][4];
#pragma unroll
    for (int mt = 0; mt < 2; mt++)
#pragma unroll
        for (int j = 0; j < 8; j++)
#pragma unroll
            for (int c = 0; c < 4; c++) d[mt][j][c] = 0.0f;

    // ---- prefetch chunk 0 into registers ----
    float4 xa[3], wb[4];
#pragma unroll
    for (int i = 0; i < 3; i++) {
        int idx = tid + i * 384;
        if (i < 2 || tid < 256)
            xa[i] = tf32x4(*(const float4*)(
                x + (size_t)(rowBase + (idx >> 3)) * CC + (idx & 7) * 4));
    }
#pragma unroll
    for (int i = 0; i < 4; i++) {
        int idx = tid + i * 384;
        int mm = idx >> 9;
        const float* Wp = (mm == 0) ? Wq : (mm == 1) ? Wk : Wv;
        int r  = (idx >> 4) & 31;
        int f4 = idx & 15;
        wb[i] = tf32x4(*(const float4*)(Wp + (size_t)r * HH + f4 * 4));
    }

    for (int kt = 0; kt < 32; kt++) {
        __syncthreads();   // previous chunk's compute done
        // ---- store prefetched regs to smem ----
#pragma unroll
        for (int i = 0; i < 3; i++) {
            int idx = tid + i * 384;
            if (i < 2 || tid < 256)
                *(float4*)(&As[idx >> 3][(idx & 7) * 4]) = xa[i];
        }
#pragma unroll
        for (int i = 0; i < 4; i++) {
            int idx = tid + i * 384;
            *(float4*)(&Bs[idx >> 9][(idx >> 4) & 31][(idx & 15) * 4]) = wb[i];
        }
        // ---- issue prefetch for next chunk (overlaps with compute) ----
        if (kt < 31) {
            const int k0n = (kt + 1) * KC;
#pragma unroll
            for (int i = 0; i < 3; i++) {
                int idx = tid + i * 384;
                if (i < 2 || tid < 256)
                    xa[i] = tf32x4(*(const float4*)(
                        x + (size_t)(rowBase + (idx >> 3)) * CC + k0n + (idx & 7) * 4));
            }
#pragma unroll
            for (int i = 0; i < 4; i++) {
                int idx = tid + i * 384;
                int mm = idx >> 9;
                const float* Wp = (mm == 0) ? Wq : (mm == 1) ? Wk : Wv;
                int r  = (idx >> 4) & 31;
                int f4 = idx & 15;
                wb[i] = tf32x4(*(const float4*)(Wp + (size_t)(k0n + r) * HH + f4 * 4));
            }
        }
        __syncthreads();   // smem tiles ready

        // ---- 4 k8-steps of m16n8k8 mma ----
#pragma unroll
        for (int ks = 0; ks < 4; ks++) {
            const int kk = ks * 8;
            uint32_t a[2][4];
#pragma unroll
            for (int mt = 0; mt < 2; mt++) {
                const int r0 = s * 32 + mt * 16 + g;
                a[mt][0] = __float_as_uint(As[r0][kk + t4]);
                a[mt][1] = __float_as_uint(As[r0 + 8][kk + t4]);
                a[mt][2] = __float_as_uint(As[r0][kk + t4 + 4]);
                a[mt][3] = __float_as_uint(As[r0 + 8][kk + t4 + 4]);
            }
            uint32_t b[8][2];
#pragma unroll
            for (int j = 0; j < 8; j++) {
                b[j][0] = __float_as_uint(Bs[m][kk + t4][j * 8 + g]);
                b[j][1] = __float_as_uint(Bs[m][kk + t4 + 4][j * 8 + g]);
            }
#pragma unroll
            for (int mt = 0; mt < 2; mt++)
#pragma unroll
                for (int j = 0; j < 8; j++)
                    mma_tf32(d[mt][j], a[mt], b[j]);
        }
    }

    // ---- epilogue: D fragments -> global ----
    float* out = (m == 0) ? g_q : (m == 1) ? g_k : g_v;
#pragma unroll
    for (int mt = 0; mt < 2; mt++) {
        const int r0 = rowBase + s * 32 + mt * 16 + g;
#pragma unroll
        for (int j = 0; j < 8; j++) {
            const int n = j * 8 + 2 * t4;
            *(float2*)(out + (size_t)r0 * HH + n) =
                make_float2(d[mt][j][0], d[mt][j][1]);
            *(float2*)(out + (size_t)(r0 + 8) * HH + n) =
                make_float2(d[mt][j][2], d[mt][j][3]);
        }
    }
}

// ===========================================================================
// Split-KV flash attention (R5 proven version, scalar FFMA).
// ===========================================================================
__global__ __launch_bounds__(256, 3) void attn_kernel()
{
    __shared__ float Qs[BQ * HH];
    __shared__ float Ks[BKT * HH];
    __shared__ float Vs[BKT * HH];
    float* Ps = Ks;  // P overwrites K after S-phase (sync-guarded)

    const int qt    = blockIdx.x;
    const int split = blockIdx.y;
    const int b     = blockIdx.z;
    const int nspl  = (qt + CHUNK) / CHUNK;
    if (split >= nspl) return;

    const int ktBeg = split * CHUNK;
    const int ktEnd = min(ktBeg + CHUNK, qt + 1);
    const int qbase = qt * BQ;

    const float* qg = g_q + ((size_t)b * TT + qbase) * HH;
    const float* kg = g_k + (size_t)b * TT * HH;
    const float* vg = g_v + (size_t)b * TT * HH;

    const int tid = threadIdx.x;
    const int ty = tid >> 4;
    const int tx = tid & 15;

#pragma unroll
    for (int it = 0; it < 4; it++) {
        int idx = tid + it * 256;
        int row = idx >> 4;
        int h4  = (idx & 15) * 4;
        float4 v = *(const float4*)(qg + row * HH + h4);
        *(float4*)(&Qs[row * HH + ((h4 + 4 * row) & 63)]) = v;
    }

    float m_i[4], l_i[4], o[4][4];
#pragma unroll
    for (int i = 0; i < 4; i++) {
        m_i[i] = -3.0e38f;
        l_i[i] = 0.0f;
#pragma unroll
        for (int c = 0; c < 4; c++) o[i][c] = 0.0f;
    }

    const float scale = 0.03125f;  // 1024^-0.5

    for (int kt = ktBeg; kt < ktEnd; kt++) {
        const int kbase = kt * BKT;

        __syncthreads();
#pragma unroll
        for (int it = 0; it < 4; it++) {
            int idx = tid + it * 256;
            int row = idx >> 4;
            int h4  = (idx & 15) * 4;
            float4 kv = *(const float4*)(kg + (size_t)(kbase + row) * HH + h4);
            *(float4*)(&Ks[row * HH + ((h4 + 4 * row) & 63)]) = kv;
            float4 vv = *(const float4*)(vg + (size_t)(kbase + row) * HH + h4);
            *(float4*)(&Vs[row * HH + h4]) = vv;
        }
        __syncthreads();

        float s[4][4];
#pragma unroll
        for (int i = 0; i < 4; i++)
#pragma unroll
            for (int j = 0; j < 4; j++) s[i][j] = 0.0f;

#pragma unroll 4
        for (int h = 0; h < HH; h += 4) {
            float4 qv[4], kv[4];
#pragma unroll
            for (int i = 0; i < 4; i++) {
                int r = ty * 4 + i;
                qv[i] = *(const float4*)(&Qs[r * HH + ((h + 4 * r) & 63)]);
            }
#pragma unroll
            for (int j = 0; j < 4; j++) {
                int c = tx * 4 + j;
                kv[j] = *(const float4*)(&Ks[c * HH + ((h + 4 * c) & 63)]);
            }
#pragma unroll
            for (int i = 0; i < 4; i++)
#pragma unroll
                for (int j = 0; j < 4; j++) {
                    s[i][j] = fmaf(qv[i].x, kv[j].x, s[i][j]);
                    s[i][j] = fmaf(qv[i].y, kv[j].y, s[i][j]);
                    s[i][j] = fmaf(qv[i].z, kv[j].z, s[i][j]);
                    s[i][j] = fmaf(qv[i].w, kv[j].w, s[i][j]);
                }
        }

        const bool diag = (kt == qt);
        float p[4][4];
#pragma unroll
        for (int i = 0; i < 4; i++) {
            const int row = qbase + ty * 4 + i;
            float mx = -3.0e38f;
#pragma unroll
            for (int j = 0; j < 4; j++) {
                float sv = s[i][j] * scale;
                if (diag && (kbase + tx * 4 + j) > row) sv = -3.0e38f;
                s[i][j] = sv;
                mx = fmaxf(mx, sv);
            }
#pragma unroll
            for (int off = 8; off; off >>= 1)
                mx = fmaxf(mx, __shfl_xor_sync(0xffffffffu, mx, off));
            const float mnew = fmaxf(m_i[i], mx);
            const float corr = __expf(m_i[i] - mnew);
            float rsum = 0.0f;
#pragma unroll
            for (int j = 0; j < 4; j++) {
                float pv = __expf(s[i][j] - mnew);
                p[i][j] = pv;
                rsum += pv;
            }
#pragma unroll
            for (int off = 8; off; off >>= 1)
                rsum += __shfl_xor_sync(0xffffffffu, rsum, off);
            l_i[i] = l_i[i] * corr + rsum;
            m_i[i] = mnew;
#pragma unroll
            for (int c = 0; c < 4; c++) o[i][c] *= corr;
        }

        __syncthreads();
#pragma unroll
        for (int i = 0; i < 4; i++) {
            *(float4*)(&Ps[(ty * 4 + i) * BKT + tx * 4]) =
                make_float4(p[i][0], p[i][1], p[i][2], p[i][3]);
        }
        __syncthreads();

#pragma unroll 4
        for (int j4 = 0; j4 < BKT / 4; j4++) {
            float4 v0 = *(const float4*)(&Vs[(4 * j4 + 0) * HH + tx * 4]);
            float4 v1 = *(const float4*)(&Vs[(4 * j4 + 1) * HH + tx * 4]);
            float4 v2 = *(const float4*)(&Vs[(4 * j4 + 2) * HH + tx * 4]);
            float4 v3 = *(const float4*)(&Vs[(4 * j4 + 3) * HH + tx * 4]);
#pragma unroll
            for (int i = 0; i < 4; i++) {
                float4 pv = *(const float4*)(&Ps[(ty * 4 + i) * BKT + 4 * j4]);
                o[i][0] = fmaf(pv.x, v0.x, o[i][0]);
                o[i][1] = fmaf(pv.x, v0.y, o[i][1]);
                o[i][2] = fmaf(pv.x, v0.z, o[i][2]);
                o[i][3] = fmaf(pv.x, v0.w, o[i][3]);
                o[i][0] = fmaf(pv.y, v1.x, o[i][0]);
                o[i][1] = fmaf(pv.y, v1.y, o[i][1]);
                o[i][2] = fmaf(pv.y, v1.z, o[i][2]);
                o[i][3] = fmaf(pv.y, v1.w, o[i][3]);
                o[i][0] = fmaf(pv.z, v2.x, o[i][0]);
                o[i][1] = fmaf(pv.z, v2.y, o[i][1]);
                o[i][2] = fmaf(pv.z, v2.z, o[i][2]);
                o[i][3] = fmaf(pv.z, v2.w, o[i][3]);
                o[i][0] = fmaf(pv.w, v3.x, o[i][0]);
                o[i][1] = fmaf(pv.w, v3.y, o[i][1]);
                o[i][2] = fmaf(pv.w, v3.z, o[i][2]);
                o[i][3] = fmaf(pv.w, v3.w, o[i][3]);
            }
        }
    }

    const size_t pidx = (size_t)((b * NT + qt) * MAXSPL + split);
    float* op = g_opart + pidx * (BQ * HH);
#pragma unroll
    for (int i = 0; i < 4; i++) {
        *(float4*)(op + (ty * 4 + i) * HH + tx * 4) =
            make_float4(o[i][0], o[i][1], o[i][2], o[i][3]);
        if (tx == 0) {
            g_mpart[pidx * BQ + ty * 4 + i] = m_i[i];
            g_lpart[pidx * BQ + ty * 4 + i] = l_i[i];
        }
    }
}

// ===========================================================================
// Merge: combine <= MAXSPL partials per row.
// ===========================================================================
__global__ __launch_bounds__(256) void merge_kernel(float* __restrict__ out)
{
    const int gid = blockIdx.x * 256 + threadIdx.x;
    const int row = gid >> 4;
    const int cx  = (gid & 15) * 4;
    const int b  = row >> 12;
    const int t  = row & (TT - 1);
    const int qt = t >> 6;
    const int r  = t & (BQ - 1);
    const int ns = (qt + CHUNK) / CHUNK;

    const size_t mlBase = (size_t)(b * NT + qt) * MAXSPL * BQ + r;

    float M = -3.0e38f;
    for (int s = 0; s < ns; s++)
        M = fmaxf(M, g_mpart[mlBase + (size_t)s * BQ]);

    float L = 0.0f;
    float a0 = 0.0f, a1 = 0.0f, a2 = 0.0f, a3 = 0.0f;
    for (int s = 0; s < ns; s++) {
        const float w = __expf(g_mpart[mlBase + (size_t)s * BQ] - M);
        L += w * g_lpart[mlBase + (size_t)s * BQ];
        const float* op = g_opart
            + (size_t)((b * NT + qt) * MAXSPL + s) * (BQ * HH) + r * HH + cx;
        float4 v = *(const float4*)op;
        a0 = fmaf(w, v.x, a0);
        a1 = fmaf(w, v.y, a1);
        a2 = fmaf(w, v.z, a2);
        a3 = fmaf(w, v.w, a3);
    }
    const float inv = 1.0f / L;
    *(float4*)(out + (size_t)row * HH + cx) =
        make_float4(a0 * inv, a1 * inv, a2 * inv, a3 * inv);
}

// ===========================================================================
extern "C" void kernel_launch(void* const* d_in, const int* in_sizes, int n_in,
                              void* d_out, int out_size)
{
    const float* x  = (const float*)d_in[0];
    const float* Wk = (const float*)d_in[1];
    const float* Wq = (const float*)d_in[2];
    const float* Wv = (const float*)d_in[3];
    float* out = (float*)d_out;

    proj_mma_kernel<<<(BB * TT) / 128, 384>>>(x, Wk, Wq, Wv);

    dim3 gAttn(NT, MAXSPL, BB);
    attn_kernel<<<gAttn, 256>>>();

    merge_kernel<<<(BB * TT * 16) / 256, 256>>>(out);
}

// round 12
// speedup vs baseline: 4.3370x; 3.4110x over previous
#include <cuda_runtime.h>
#include <cuda_fp16.h>
#include <math.h>
#include <stdint.h>

// Problem constants
#define BB 4
#define TT 4096
#define CC 1024
#define HH 64
#define BQ 128            // query rows per block (8 warps x m16)
#define BKT 64            // key rows per kt tile
#define NT (TT / BQ)      // 32 query tiles per batch
#define CHUNK 8           // kt tiles per split block
#define MAXSPL 8          // max splits = 2*32/8 = 8

// Scratch (no cudaMalloc allowed)
__device__ float g_q[BB * TT * HH];
__device__ float g_k[BB * TT * HH];
__device__ float g_v[BB * TT * HH];
__device__ float g_opart[BB * NT * MAXSPL * BQ * HH];
__device__ float g_mpart[BB * NT * MAXSPL * BQ];
__device__ float g_lpart[BB * NT * MAXSPL * BQ];

// ---- base-ISA tensor core MMAs (sm_80+, no 'a' gating) ----
__device__ __forceinline__ void mma_tf32(float* d, const uint32_t* a,
                                         uint32_t b0, uint32_t b1) {
    asm volatile(
        "mma.sync.aligned.m16n8k8.row.col.f32.tf32.tf32.f32 "
        "{%0,%1,%2,%3}, {%4,%5,%6,%7}, {%8,%9}, {%0,%1,%2,%3};"
        : "+f"(d[0]), "+f"(d[1]), "+f"(d[2]), "+f"(d[3])
        : "r"(a[0]), "r"(a[1]), "r"(a[2]), "r"(a[3]), "r"(b0), "r"(b1));
}
__device__ __forceinline__ void mma_f16(float* d, uint32_t a0, uint32_t a1,
                                        uint32_t a2, uint32_t a3,
                                        uint32_t b0, uint32_t b1) {
    asm volatile(
        "mma.sync.aligned.m16n8k16.row.col.f32.f16.f16.f32 "
        "{%0,%1,%2,%3}, {%4,%5,%6,%7}, {%8,%9}, {%0,%1,%2,%3};"
        : "+f"(d[0]), "+f"(d[1]), "+f"(d[2]), "+f"(d[3])
        : "r"(a0), "r"(a1), "r"(a2), "r"(a3), "r"(b0), "r"(b1));
}
__device__ __forceinline__ float to_tf32(float f) {
    float o;
    asm("cvt.rna.tf32.f32 %0, %1;" : "=f"(o) : "f"(f));
    return o;
}
__device__ __forceinline__ float4 tf32x4(float4 v) {
    v.x = to_tf32(v.x); v.y = to_tf32(v.y);
    v.z = to_tf32(v.z); v.w = to_tf32(v.w);
    return v;
}
// packed fp16x2: lo -> bits[15:0], hi -> bits[31:16]
__device__ __forceinline__ uint32_t pack_h2(float lo, float hi) {
    uint32_t d;
    asm("cvt.rn.f16x2.f32 %0, %1, %2;" : "=r"(d) : "f"(hi), "f"(lo));
    return d;
}

// ===========================================================================
// Projection GEMM on HMMA tf32 (verified R11): q,k,v = x @ W
// ===========================================================================
#define KC 32
__global__ __launch_bounds__(384) void proj_mma_kernel(
    const float* __restrict__ x,
    const float* __restrict__ Wk,
    const float* __restrict__ Wq,
    const float* __restrict__ Wv)
{
    __shared__ float As[128][36];
    __shared__ float Bs[3][KC][72];

    const int tid  = threadIdx.x;
    const int w    = tid >> 5;
    const int lane = tid & 31;
    const int g    = lane >> 2;
    const int t4   = lane & 3;
    const int s    = w & 3;
    const int m    = w >> 2;

    const int rowBase = blockIdx.x * 128;

    float d[2][8][4];
#pragma unroll
    for (int mt = 0; mt < 2; mt++)
#pragma unroll
        for (int j = 0; j < 8; j++)
#pragma unroll
            for (int c = 0; c < 4; c++) d[mt][j][c] = 0.0f;

    float4 xa[3], wb[4];
#pragma unroll
    for (int i = 0; i < 3; i++) {
        int idx = tid + i * 384;
        if (i < 2 || tid < 256)
            xa[i] = tf32x4(*(const float4*)(
                x + (size_t)(rowBase + (idx >> 3)) * CC + (idx & 7) * 4));
    }
#pragma unroll
    for (int i = 0; i < 4; i++) {
        int idx = tid + i * 384;
        int mm = idx >> 9;
        const float* Wp = (mm == 0) ? Wq : (mm == 1) ? Wk : Wv;
        int r  = (idx >> 4) & 31;
        int f4 = idx & 15;
        wb[i] = tf32x4(*(const float4*)(Wp + (size_t)r * HH + f4 * 4));
    }

    for (int kt = 0; kt < 32; kt++) {
        __syncthreads();
#pragma unroll
        for (int i = 0; i < 3; i++) {
            int idx = tid + i * 384;
            if (i < 2 || tid < 256)
                *(float4*)(&As[idx >> 3][(idx & 7) * 4]) = xa[i];
        }
#pragma unroll
        for (int i = 0; i < 4; i++) {
            int idx = tid + i * 384;
            *(float4*)(&Bs[idx >> 9][(idx >> 4) & 31][(idx & 15) * 4]) = wb[i];
        }
        if (kt < 31) {
            const int k0n = (kt + 1) * KC;
#pragma unroll
            for (int i = 0; i < 3; i++) {
                int idx = tid + i * 384;
                if (i < 2 || tid < 256)
                    xa[i] = tf32x4(*(const float4*)(
                        x + (size_t)(rowBase + (idx >> 3)) * CC + k0n + (idx & 7) * 4));
            }
#pragma unroll
            for (int i = 0; i < 4; i++) {
                int idx = tid + i * 384;
                int mm = idx >> 9;
                const float* Wp = (mm == 0) ? Wq : (mm == 1) ? Wk : Wv;
                int r  = (idx >> 4) & 31;
                int f4 = idx & 15;
                wb[i] = tf32x4(*(const float4*)(Wp + (size_t)(k0n + r) * HH + f4 * 4));
            }
        }
        __syncthreads();

#pragma unroll
        for (int ks = 0; ks < 4; ks++) {
            const int kk = ks * 8;
            uint32_t a[2][4];
#pragma unroll
            for (int mt = 0; mt < 2; mt++) {
                const int r0 = s * 32 + mt * 16 + g;
                a[mt][0] = __float_as_uint(As[r0][kk + t4]);
                a[mt][1] = __float_as_uint(As[r0 + 8][kk + t4]);
                a[mt][2] = __float_as_uint(As[r0][kk + t4 + 4]);
                a[mt][3] = __float_as_uint(As[r0 + 8][kk + t4 + 4]);
            }
            uint32_t b[8][2];
#pragma unroll
            for (int j = 0; j < 8; j++) {
                b[j][0] = __float_as_uint(Bs[m][kk + t4][j * 8 + g]);
                b[j][1] = __float_as_uint(Bs[m][kk + t4 + 4][j * 8 + g]);
            }
#pragma unroll
            for (int mt = 0; mt < 2; mt++)
#pragma unroll
                for (int j = 0; j < 8; j++)
                    mma_tf32(d[mt][j], a[mt], b[j][0], b[j][1]);
        }
    }

    float* out = (m == 0) ? g_q : (m == 1) ? g_k : g_v;
#pragma unroll
    for (int mt = 0; mt < 2; mt++) {
        const int r0 = rowBase + s * 32 + mt * 16 + g;
#pragma unroll
        for (int j = 0; j < 8; j++) {
            const int n = j * 8 + 2 * t4;
            *(float2*)(out + (size_t)r0 * HH + n) =
                make_float2(d[mt][j][0], d[mt][j][1]);
            *(float2*)(out + (size_t)(r0 + 8) * HH + n) =
                make_float2(d[mt][j][2], d[mt][j][3]);
        }
    }
}

// ===========================================================================
// MMA flash attention (split-KV, causal). 256 threads = 8 warps, each warp
// owns 16 query rows. S: tf32 m16n8k8 (Q frags in regs). Softmax on C frags.
// P packed to fp16 in regs (C layout == fp16 A layout). PV: fp16 m16n8k16,
// V as key-pair-interleaved fp16x2. Smem 34.8KB (Qs aliases Ks+Vsi).
// ===========================================================================
#define KS_STRIDE 68
#define VS_STRIDE 72
__global__ __launch_bounds__(256) void attn_mma_kernel()
{
    __shared__ __align__(16) char pool[128 * KS_STRIDE * 4];  // 34816 B
    float*    Qs  = (float*)pool;                       // [128][68] (init only)
    float*    Ks  = (float*)pool;                       // [64][68]
    uint32_t* Vsi = (uint32_t*)(pool + 64 * KS_STRIDE * 4);  // [32][72] fp16x2

    const int qt    = blockIdx.x;
    const int split = blockIdx.y;
    const int b     = blockIdx.z;
    const int KTQ   = 2 * (qt + 1);
    const int nspl  = (KTQ + CHUNK - 1) / CHUNK;
    if (split >= nspl) return;

    const int ktBeg = split * CHUNK;
    const int ktEnd = min(ktBeg + CHUNK, KTQ);
    const int qbase = qt * BQ;

    const float* qg = g_q + ((size_t)b * TT + qbase) * HH;
    const float* kg = g_k + (size_t)b * TT * HH;
    const float* vg = g_v + (size_t)b * TT * HH;

    const int tid  = threadIdx.x;
    const int w    = tid >> 5;
    const int lane = tid & 31;
    const int g    = lane >> 2;
    const int t4   = lane & 3;
    const int r0   = w * 16;          // warp's first query row (block-local)

    // ---- load Q tile -> smem (tf32), extract A fragments, release smem ----
#pragma unroll
    for (int it = 0; it < 8; it++) {
        int idx = tid + it * 256;
        int row = idx >> 4;
        int h4  = (idx & 15) * 4;
        *(float4*)(&Qs[row * KS_STRIDE + h4]) =
            tf32x4(*(const float4*)(qg + (size_t)row * HH + h4));
    }
    __syncthreads();
    uint32_t qa[8][4];
#pragma unroll
    for (int ks = 0; ks < 8; ks++) {
        qa[ks][0] = __float_as_uint(Qs[(r0 + g) * KS_STRIDE + 8 * ks + t4]);
        qa[ks][1] = __float_as_uint(Qs[(r0 + g + 8) * KS_STRIDE + 8 * ks + t4]);
        qa[ks][2] = __float_as_uint(Qs[(r0 + g) * KS_STRIDE + 8 * ks + t4 + 4]);
        qa[ks][3] = __float_as_uint(Qs[(r0 + g + 8) * KS_STRIDE + 8 * ks + t4 + 4]);
    }

    float m0 = -3.0e38f, m1 = -3.0e38f, l0 = 0.0f, l1 = 0.0f;
    float o[8][4];
#pragma unroll
    for (int j = 0; j < 8; j++)
#pragma unroll
        for (int c = 0; c < 4; c++) o[j][c] = 0.0f;

    const float scale = 0.03125f;  // 1024^-0.5

    for (int kt = ktBeg; kt < ktEnd; kt++) {
        const int kbase = kt * BKT;

        __syncthreads();  // prior S/PV smem reads done (also covers Qs init)
        // ---- load K tile (tf32, [key][h]) ----
#pragma unroll
        for (int it = 0; it < 4; it++) {
            int idx = tid + it * 256;
            int row = idx >> 4;
            int h4  = (idx & 15) * 4;
            *(float4*)(&Ks[row * KS_STRIDE + h4]) =
                tf32x4(*(const float4*)(kg + (size_t)(kbase + row) * HH + h4));
        }
        // ---- load V tile as fp16x2 key pairs: Vsi[p][h] = {V[2p][h], V[2p+1][h]} ----
#pragma unroll
        for (int it = 0; it < 2; it++) {
            int idx = tid + it * 256;
            int p  = idx >> 4;
            int h4 = (idx & 15) * 4;
            float4 va = *(const float4*)(vg + (size_t)(kbase + 2 * p) * HH + h4);
            float4 vb = *(const float4*)(vg + (size_t)(kbase + 2 * p + 1) * HH + h4);
            uint32_t* dst = &Vsi[p * VS_STRIDE + h4];
            dst[0] = pack_h2(va.x, vb.x);
            dst[1] = pack_h2(va.y, vb.y);
            dst[2] = pack_h2(va.z, vb.z);
            dst[3] = pack_h2(va.w, vb.w);
        }
        __syncthreads();

        // Warp-uniform skip: tile entirely above this warp's rows would be
        // fully masked (exp(0)=1 garbage). Rows qbase+r0 .. qbase+r0+15.
        if (kbase > qbase + r0 + 15) continue;

        // ---- S = Q K^T (8 n8-tiles of keys x 8 k8-steps of h) ----
        float s[8][4];
#pragma unroll
        for (int j = 0; j < 8; j++)
#pragma unroll
            for (int c = 0; c < 4; c++) s[j][c] = 0.0f;

#pragma unroll
        for (int j = 0; j < 8; j++) {
            const float* kr = &Ks[(8 * j + g) * KS_STRIDE];
#pragma unroll
            for (int ks = 0; ks < 8; ks++) {
                uint32_t b0 = __float_as_uint(kr[8 * ks + t4]);
                uint32_t b1 = __float_as_uint(kr[8 * ks + t4 + 4]);
                mma_tf32(s[j], qa[ks], b0, b1);
            }
        }

        // ---- scale + causal mask ----
        const int row0 = qbase + r0 + g;
        const int row1 = row0 + 8;
        if (kbase + BKT - 1 > qbase + r0) {
#pragma unroll
            for (int j = 0; j < 8; j++) {
                const int c0 = kbase + 8 * j + 2 * t4;
                s[j][0] = (c0     > row0) ? -3.0e38f : s[j][0] * scale;
                s[j][1] = (c0 + 1 > row0) ? -3.0e38f : s[j][1] * scale;
                s[j][2] = (c0     > row1) ? -3.0e38f : s[j][2] * scale;
                s[j][3] = (c0 + 1 > row1) ? -3.0e38f : s[j][3] * scale;
            }
        } else {
#pragma unroll
            for (int j = 0; j < 8; j++)
#pragma unroll
                for (int c = 0; c < 4; c++) s[j][c] *= scale;
        }

        // ---- online softmax on fragments (row reduce across quad t4) ----
        float mx0 = -3.0e38f, mx1 = -3.0e38f;
#pragma unroll
        for (int j = 0; j < 8; j++) {
            mx0 = fmaxf(mx0, fmaxf(s[j][0], s[j][1]));
            mx1 = fmaxf(mx1, fmaxf(s[j][2], s[j][3]));
        }
        mx0 = fmaxf(mx0, __shfl_xor_sync(0xffffffffu, mx0, 1));
        mx0 = fmaxf(mx0, __shfl_xor_sync(0xffffffffu, mx0, 2));
        mx1 = fmaxf(mx1, __shfl_xor_sync(0xffffffffu, mx1, 1));
        mx1 = fmaxf(mx1, __shfl_xor_sync(0xffffffffu, mx1, 2));

        const float mn0 = fmaxf(m0, mx0);
        const float mn1 = fmaxf(m1, mx1);
        const float cr0 = __expf(m0 - mn0);
        const float cr1 = __expf(m1 - mn1);

        float rs0 = 0.0f, rs1 = 0.0f;
        uint32_t pa0[8], pa1[8];   // fp16x2 A-frag halves: rows g / g+8
#pragma unroll
        for (int j = 0; j < 8; j++) {
            float p0 = __expf(s[j][0] - mn0);
            float p1 = __expf(s[j][1] - mn0);
            float p2 = __expf(s[j][2] - mn1);
            float p3 = __expf(s[j][3] - mn1);
            rs0 += p0 + p1;
            rs1 += p2 + p3;
            pa0[j] = pack_h2(p0, p1);
            pa1[j] = pack_h2(p2, p3);
        }
        rs0 += __shfl_xor_sync(0xffffffffu, rs0, 1);
        rs0 += __shfl_xor_sync(0xffffffffu, rs0, 2);
        rs1 += __shfl_xor_sync(0xffffffffu, rs1, 1);
        rs1 += __shfl_xor_sync(0xffffffffu, rs1, 2);

        l0 = l0 * cr0 + rs0;
        l1 = l1 * cr1 + rs1;
        m0 = mn0;
        m1 = mn1;
#pragma unroll
        for (int j = 0; j < 8; j++) {
            o[j][0] *= cr0; o[j][1] *= cr0;
            o[j][2] *= cr1; o[j][3] *= cr1;
        }

        // ---- O += P V (fp16 m16n8k16, P straight from registers) ----
#pragma unroll
        for (int kc = 0; kc < 4; kc++) {
            const uint32_t a0 = pa0[2 * kc],     a1 = pa1[2 * kc];
            const uint32_t a2 = pa0[2 * kc + 1], a3 = pa1[2 * kc + 1];
            const uint32_t* v0 = &Vsi[(8 * kc + t4) * VS_STRIDE];
            const uint32_t* v1 = &Vsi[(8 * kc + t4 + 4) * VS_STRIDE];
#pragma unroll
            for (int jn = 0; jn < 8; jn++) {
                mma_f16(o[jn], a0, a1, a2, a3, v0[8 * jn + g], v1[8 * jn + g]);
            }
        }
    }

    // ---- epilogue: unnormalized partial + row stats ----
    const size_t pidx = (size_t)((b * NT + qt) * MAXSPL + split);
    float* op = g_opart + pidx * (BQ * HH);
#pragma unroll
    for (int jn = 0; jn < 8; jn++) {
        const int n = 8 * jn + 2 * t4;
        *(float2*)(op + (size_t)(r0 + g) * HH + n)     = make_float2(o[jn][0], o[jn][1]);
        *(float2*)(op + (size_t)(r0 + g + 8) * HH + n) = make_float2(o[jn][2], o[jn][3]);
    }
    if (t4 == 0) {
        g_mpart[pidx * BQ + r0 + g]     = m0;
        g_mpart[pidx * BQ + r0 + g + 8] = m1;
        g_lpart[pidx * BQ + r0 + g]     = l0;
        g_lpart[pidx * BQ + r0 + g + 8] = l1;
    }
}

// ===========================================================================
// Merge: combine <= MAXSPL partials per row (BQ=128 indexing).
// ===========================================================================
__global__ __launch_bounds__(256) void merge_kernel(float* __restrict__ out)
{
    const int gid = blockIdx.x * 256 + threadIdx.x;
    const int row = gid >> 4;
    const int cx  = (gid & 15) * 4;
    const int b  = row >> 12;
    const int t  = row & (TT - 1);
    const int qt = t >> 7;             // t / BQ
    const int r  = t & (BQ - 1);
    const int ns = (2 * (qt + 1) + CHUNK - 1) / CHUNK;

    const size_t mlBase = (size_t)(b * NT + qt) * MAXSPL * BQ + r;

    float M = -3.0e38f;
    for (int s = 0; s < ns; s++)
        M = fmaxf(M, g_mpart[mlBase + (size_t)s * BQ]);

    float L = 0.0f;
    float a0 = 0.0f, a1 = 0.0f, a2 = 0.0f, a3 = 0.0f;
    for (int s = 0; s < ns; s++) {
        const float wgt = __expf(g_mpart[mlBase + (size_t)s * BQ] - M);
        L += wgt * g_lpart[mlBase + (size_t)s * BQ];
        const float* op = g_opart
            + (size_t)((b * NT + qt) * MAXSPL + s) * (BQ * HH) + r * HH + cx;
        float4 v = *(const float4*)op;
        a0 = fmaf(wgt, v.x, a0);
        a1 = fmaf(wgt, v.y, a1);
        a2 = fmaf(wgt, v.z, a2);
        a3 = fmaf(wgt, v.w, a3);
    }
    const float inv = 1.0f / L;
    *(float4*)(out + (size_t)row * HH + cx) =
        make_float4(a0 * inv, a1 * inv, a2 * inv, a3 * inv);
}

// ===========================================================================
extern "C" void kernel_launch(void* const* d_in, const int* in_sizes, int n_in,
                              void* d_out, int out_size)
{
    const float* x  = (const float*)d_in[0];
    const float* Wk = (const float*)d_in[1];
    const float* Wq = (const float*)d_in[2];
    const float* Wv = (const float*)d_in[3];
    float* out = (float*)d_out;

    proj_mma_kernel<<<(BB * TT) / 128, 384>>>(x, Wk, Wq, Wv);

    dim3 gAttn(NT, MAXSPL, BB);
    attn_mma_kernel<<<gAttn, 256>>>();

    merge_kernel<<<(BB * TT * 16) / 256, 256>>>(out);
}

// round 13
// speedup vs baseline: 7.7513x; 1.7872x over previous
#include <cuda_runtime.h>
#include <cuda_fp16.h>
#include <math.h>
#include <stdint.h>

// Problem constants
#define BB 4
#define TT 4096
#define CC 1024
#define HH 64
#define BQ 128            // attn query rows per block (8 warps x m16)
#define BKT 64            // key rows per kt tile
#define NT (TT / BQ)      // 32 query tiles per batch
#define CHUNK 8           // kt tiles per split block
#define MAXSPL 8

// Scratch (no cudaMalloc allowed)
__device__ __half g_wh[3 * CC * HH];        // fp16 W (q,k,v order)
__device__ __half g_qh[BB * TT * HH];       // fp16 q
__device__ __half g_kh[BB * TT * HH];       // fp16 k
__device__ float  g_v [BB * TT * HH];       // fp32 v
__device__ float g_opart[BB * NT * MAXSPL * BQ * HH];
__device__ float g_mpart[BB * NT * MAXSPL * BQ];
__device__ float g_lpart[BB * NT * MAXSPL * BQ];

// ---- base-ISA helpers (all sm_75/80+, pass the sm_103 base-target gate) ----
__device__ __forceinline__ void mma_f16(float* d, uint32_t a0, uint32_t a1,
                                        uint32_t a2, uint32_t a3,
                                        uint32_t b0, uint32_t b1) {
    asm volatile(
        "mma.sync.aligned.m16n8k16.row.col.f32.f16.f16.f32 "
        "{%0,%1,%2,%3}, {%4,%5,%6,%7}, {%8,%9}, {%0,%1,%2,%3};"
        : "+f"(d[0]), "+f"(d[1]), "+f"(d[2]), "+f"(d[3])
        : "r"(a0), "r"(a1), "r"(a2), "r"(a3), "r"(b0), "r"(b1));
}
__device__ __forceinline__ void ldm_x4(uint32_t* r, uint32_t saddr) {
    asm volatile("ldmatrix.sync.aligned.m8n8.x4.shared.b16 {%0,%1,%2,%3}, [%4];"
                 : "=r"(r[0]), "=r"(r[1]), "=r"(r[2]), "=r"(r[3]) : "r"(saddr));
}
__device__ __forceinline__ void ldm_x4_t(uint32_t* r, uint32_t saddr) {
    asm volatile("ldmatrix.sync.aligned.m8n8.x4.trans.shared.b16 {%0,%1,%2,%3}, [%4];"
                 : "=r"(r[0]), "=r"(r[1]), "=r"(r[2]), "=r"(r[3]) : "r"(saddr));
}
__device__ __forceinline__ uint32_t smem_u32(const void* p) {
    uint32_t a;
    asm("{ .reg .u64 t; cvta.to.shared.u64 t, %1; cvt.u32.u64 %0, t; }"
        : "=r"(a) : "l"(p));
    return a;
}
// packed fp16x2: lo -> bits[15:0], hi -> bits[31:16]
__device__ __forceinline__ uint32_t pack_h2(float lo, float hi) {
    uint32_t d;
    asm("cvt.rn.f16x2.f32 %0, %1, %2;" : "=r"(d) : "f"(hi), "f"(lo));
    return d;
}
__device__ __forceinline__ uint2 f4_to_h4(float4 v) {
    return make_uint2(pack_h2(v.x, v.y), pack_h2(v.z, v.w));
}

// ===========================================================================
// Prep: W fp32 -> fp16 copy into g_wh (q,k,v order). grid 192 x 256.
// ===========================================================================
__global__ __launch_bounds__(256) void prep_w_kernel(
    const float* __restrict__ Wk,
    const float* __restrict__ Wq,
    const float* __restrict__ Wv)
{
    const int idx = blockIdx.x * 256 + threadIdx.x;   // 0 .. 49151 float4s
    const int mm  = idx >> 14;                        // 16384 float4 / matrix
    const int e4  = idx & 16383;
    const float* W = (mm == 0) ? Wq : (mm == 1) ? Wk : Wv;
    float4 v = ((const float4*)W)[e4];
    *(uint2*)(g_wh + (size_t)mm * (CC * HH) + e4 * 4) = f4_to_h4(v);
}

// ===========================================================================
// Projection on fp16 HMMA + ldmatrix. grid 256 x 384 (12 warps).
// Block: 64 x-rows. Warp w: m = w>>2 (q/k/v), slice s = w&3 (16 rows).
// K loop: 16 chunks of 64. Smem: Ah[64][72]h, Bh[3][64][72]h (36.9 KB).
// ===========================================================================
__global__ __launch_bounds__(384, 2) void proj_mma_kernel(
    const float* __restrict__ x)
{
    __shared__ __align__(16) __half Ah[64 * 72];
    __shared__ __align__(16) __half Bh[3 * 64 * 72];

    const int tid  = threadIdx.x;
    const int lane = tid & 31;
    const int w    = tid >> 5;
    const int g    = lane >> 2;
    const int t4   = lane & 3;
    const int m    = w >> 2;        // 0=q 1=k 2=v
    const int r0   = (w & 3) * 16;  // slice rows

    const int rowBase = blockIdx.x * 64;

    const uint32_t aBase = smem_u32(Ah);
    const uint32_t bBase = smem_u32(Bh) + m * 9216;
    // fragment base addresses (bytes); +ks*32B steps cols, +2304B steps 16 k-rows
    const uint32_t aAddr0 = aBase + (((r0 + (lane & 15)) * 72 + 8 * (lane >> 4)) << 1);
    const uint32_t bAddr0 = bBase + ((((lane & 15)) * 72 + 8 * (lane >> 4)) << 1);

    float d[8][4];
#pragma unroll
    for (int j = 0; j < 8; j++)
#pragma unroll
        for (int c = 0; c < 4; c++) d[j][c] = 0.0f;

    // prefetch x chunk 0 (fp32 regs; cvt at store)
    float4 xa[3];
#pragma unroll
    for (int it = 0; it < 3; it++) {
        int idx = tid + it * 384;
        if (idx < 1024)
            xa[it] = *(const float4*)(
                x + (size_t)(rowBase + (idx >> 4)) * CC + (idx & 15) * 4);
    }

    for (int kt = 0; kt < 16; kt++) {
        const int k0 = kt * 64;
        __syncthreads();   // prior chunk compute done
        // store x tile (cvt fp16)
#pragma unroll
        for (int it = 0; it < 3; it++) {
            int idx = tid + it * 384;
            if (idx < 1024)
                *(uint2*)(Ah + (idx >> 4) * 72 + (idx & 15) * 4) = f4_to_h4(xa[it]);
        }
        // W tiles: fp16 direct copy (L2-hot)
#pragma unroll
        for (int it = 0; it < 4; it++) {
            int idx = tid + it * 384;          // 0..1535 uint4
            int mm  = idx >> 9;
            int kr  = (idx >> 3) & 63;
            int c8  = (idx & 7) * 8;
            *(uint4*)(Bh + mm * 4608 + kr * 72 + c8) =
                *(const uint4*)(g_wh + (size_t)mm * (CC * HH) + (size_t)(k0 + kr) * HH + c8);
        }
        // prefetch next x chunk
        if (kt < 15) {
#pragma unroll
            for (int it = 0; it < 3; it++) {
                int idx = tid + it * 384;
                if (idx < 1024)
                    xa[it] = *(const float4*)(
                        x + (size_t)(rowBase + (idx >> 4)) * CC + k0 + 64 + (idx & 15) * 4);
            }
        }
        __syncthreads();   // tiles ready

        // 4 k16 steps x (1 A-ldmatrix + 4 B-ldmatrix + 8 MMA)
#pragma unroll
        for (int ks = 0; ks < 4; ks++) {
            uint32_t a[4];
            ldm_x4(a, aAddr0 + ks * 32);
#pragma unroll
            for (int jp = 0; jp < 4; jp++) {
                uint32_t bf[4];
                ldm_x4_t(bf, bAddr0 + ks * 2304 + jp * 32);
                mma_f16(d[2 * jp],     a[0], a[1], a[2], a[3], bf[0], bf[1]);
                mma_f16(d[2 * jp + 1], a[0], a[1], a[2], a[3], bf[2], bf[3]);
            }
        }
    }

    // epilogue: q,k as fp16; v as fp32
    const int gr = rowBase + r0 + g;
    if (m < 2) {
        uint32_t* outh = (uint32_t*)((m == 0) ? g_qh : g_kh);
#pragma unroll
        for (int j = 0; j < 8; j++) {
            const int n = 8 * j + 2 * t4;
            outh[((size_t)gr * HH + n) >> 1]       = pack_h2(d[j][0], d[j][1]);
            outh[((size_t)(gr + 8) * HH + n) >> 1] = pack_h2(d[j][2], d[j][3]);
        }
    } else {
#pragma unroll
        for (int j = 0; j < 8; j++) {
            const int n = 8 * j + 2 * t4;
            *(float2*)(g_v + (size_t)gr * HH + n)       = make_float2(d[j][0], d[j][1]);
            *(float2*)(g_v + (size_t)(gr + 8) * HH + n) = make_float2(d[j][2], d[j][3]);
        }
    }
}

// ===========================================================================
// MMA flash attention (split-KV, causal), fp16 S via ldmatrix + fp16 PV.
// 256 threads = 8 warps x m16 rows. Smem pool 18.4 KB: Qh[128][72]h aliased
// after fragment extraction by Kh[64][72]h + Vsi[32][72]u32.
// ===========================================================================
__global__ __launch_bounds__(256) void attn_mma_kernel()
{
    __shared__ __align__(16) char pool[18432];
    __half*   Qh  = (__half*)pool;                   // [128][72]
    __half*   Kh  = (__half*)pool;                   // [64][72]
    uint32_t* Vsi = (uint32_t*)(pool + 9216);        // [32][72] fp16x2

    const int qt    = blockIdx.x;
    const int split = blockIdx.y;
    const int b     = blockIdx.z;
    const int KTQ   = 2 * (qt + 1);
    const int nspl  = (KTQ + CHUNK - 1) / CHUNK;
    if (split >= nspl) return;

    const int ktBeg = split * CHUNK;
    const int ktEnd = min(ktBeg + CHUNK, KTQ);
    const int qbase = qt * BQ;

    const __half* qgh = g_qh + ((size_t)b * TT + qbase) * HH;
    const __half* kgh = g_kh + (size_t)b * TT * HH;
    const float*  vg  = g_v  + (size_t)b * TT * HH;

    const int tid  = threadIdx.x;
    const int w    = tid >> 5;
    const int lane = tid & 31;
    const int g    = lane >> 2;
    const int t4   = lane & 3;
    const int r0   = w * 16;

    const uint32_t sBase = smem_u32(pool);
    // K-fragment address pattern (no-trans; Kh[key][h] IS col-major B)
    const int keyoff = (lane & 7) + ((lane & 16) ? 8 : 0);
    const int koff   = (lane & 8) ? 8 : 0;
    const uint32_t kAddr0 = sBase + ((keyoff * 72 + koff) << 1);

    // ---- load Q tile (fp16 direct copy), extract A fragments, release ----
#pragma unroll
    for (int it = 0; it < 4; it++) {
        int idx = tid + it * 256;          // 1024 uint4
        int row = idx >> 3;
        int c8  = (idx & 7) * 8;
        *(uint4*)(Qh + row * 72 + c8) =
            *(const uint4*)(qgh + (size_t)row * HH + c8);
    }
    __syncthreads();
    uint32_t qa[4][4];
    {
        const uint32_t qAddr0 =
            sBase + (((r0 + (lane & 15)) * 72 + 8 * (lane >> 4)) << 1);
#pragma unroll
        for (int ks = 0; ks < 4; ks++) ldm_x4(qa[ks], qAddr0 + ks * 32);
    }

    float m0 = -3.0e38f, m1 = -3.0e38f, l0 = 0.0f, l1 = 0.0f;
    float o[8][4];
#pragma unroll
    for (int j = 0; j < 8; j++)
#pragma unroll
        for (int c = 0; c < 4; c++) o[j][c] = 0.0f;

    const float scale = 0.03125f;  // 1024^-0.5

    for (int kt = ktBeg; kt < ktEnd; kt++) {
        const int kbase = kt * BKT;

        __syncthreads();  // prior reads done (also guards Qh aliasing)
        // ---- K tile: fp16 direct copy ----
#pragma unroll
        for (int it = 0; it < 2; it++) {
            int idx = tid + it * 256;      // 512 uint4
            int row = idx >> 3;
            int c8  = (idx & 7) * 8;
            *(uint4*)(Kh + row * 72 + c8) =
                *(const uint4*)(kgh + (size_t)(kbase + row) * HH + c8);
        }
        // ---- V tile: fp16x2 key pairs ----
#pragma unroll
        for (int it = 0; it < 2; it++) {
            int idx = tid + it * 256;
            int p  = idx >> 4;
            int h4 = (idx & 15) * 4;
            float4 va = *(const float4*)(vg + (size_t)(kbase + 2 * p) * HH + h4);
            float4 vb = *(const float4*)(vg + (size_t)(kbase + 2 * p + 1) * HH + h4);
            uint32_t* dst = &Vsi[p * 72 + h4];
            dst[0] = pack_h2(va.x, vb.x);
            dst[1] = pack_h2(va.y, vb.y);
            dst[2] = pack_h2(va.z, vb.z);
            dst[3] = pack_h2(va.w, vb.w);
        }
        __syncthreads();

        // warp-uniform fully-masked skip
        if (kbase > qbase + r0 + 15) continue;

        // ---- S = Q K^T : fp16 m16n8k16, K frags via ldmatrix ----
        float s[8][4];
#pragma unroll
        for (int j = 0; j < 8; j++)
#pragma unroll
            for (int c = 0; c < 4; c++) s[j][c] = 0.0f;

#pragma unroll
        for (int jp = 0; jp < 4; jp++) {
#pragma unroll
            for (int ks = 0; ks < 4; ks++) {
                uint32_t kb[4];
                ldm_x4(kb, kAddr0 + jp * 2304 + ks * 32);
                mma_f16(s[2 * jp],     qa[ks][0], qa[ks][1], qa[ks][2], qa[ks][3],
                        kb[0], kb[1]);
                mma_f16(s[2 * jp + 1], qa[ks][0], qa[ks][1], qa[ks][2], qa[ks][3],
                        kb[2], kb[3]);
            }
        }

        // ---- scale + causal mask ----
        const int row0 = qbase + r0 + g;
        const int row1 = row0 + 8;
        if (kbase + BKT - 1 > qbase + r0) {
#pragma unroll
            for (int j = 0; j < 8; j++) {
                const int c0 = kbase + 8 * j + 2 * t4;
                s[j][0] = (c0     > row0) ? -3.0e38f : s[j][0] * scale;
                s[j][1] = (c0 + 1 > row0) ? -3.0e38f : s[j][1] * scale;
                s[j][2] = (c0     > row1) ? -3.0e38f : s[j][2] * scale;
                s[j][3] = (c0 + 1 > row1) ? -3.0e38f : s[j][3] * scale;
            }
        } else {
#pragma unroll
            for (int j = 0; j < 8; j++)
#pragma unroll
                for (int c = 0; c < 4; c++) s[j][c] *= scale;
        }

        // ---- online softmax on fragments ----
        float mx0 = -3.0e38f, mx1 = -3.0e38f;
#pragma unroll
        for (int j = 0; j < 8; j++) {
            mx0 = fmaxf(mx0, fmaxf(s[j][0], s[j][1]));
            mx1 = fmaxf(mx1, fmaxf(s[j][2], s[j][3]));
        }
        mx0 = fmaxf(mx0, __shfl_xor_sync(0xffffffffu, mx0, 1));
        mx0 = fmaxf(mx0, __shfl_xor_sync(0xffffffffu, mx0, 2));
        mx1 = fmaxf(mx1, __shfl_xor_sync(0xffffffffu, mx1, 1));
        mx1 = fmaxf(mx1, __shfl_xor_sync(0xffffffffu, mx1, 2));

        const float mn0 = fmaxf(m0, mx0);
        const float mn1 = fmaxf(m1, mx1);
        const float cr0 = __expf(m0 - mn0);
        const float cr1 = __expf(m1 - mn1);

        float rs0 = 0.0f, rs1 = 0.0f;
        uint32_t pa0[8], pa1[8];
#pragma unroll
        for (int j = 0; j < 8; j++) {
            float p0 = __expf(s[j][0] - mn0);
            float p1 = __expf(s[j][1] - mn0);
            float p2 = __expf(s[j][2] - mn1);
            float p3 = __expf(s[j][3] - mn1);
            rs0 += p0 + p1;
            rs1 += p2 + p3;
            pa0[j] = pack_h2(p0, p1);
            pa1[j] = pack_h2(p2, p3);
        }
        rs0 += __shfl_xor_sync(0xffffffffu, rs0, 1);
        rs0 += __shfl_xor_sync(0xffffffffu, rs0, 2);
        rs1 += __shfl_xor_sync(0xffffffffu, rs1, 1);
        rs1 += __shfl_xor_sync(0xffffffffu, rs1, 2);

        l0 = l0 * cr0 + rs0;
        l1 = l1 * cr1 + rs1;
        m0 = mn0;
        m1 = mn1;
#pragma unroll
        for (int j = 0; j < 8; j++) {
            o[j][0] *= cr0; o[j][1] *= cr0;
            o[j][2] *= cr1; o[j][3] *= cr1;
        }

        // ---- O += P V (fp16, P from registers) ----
#pragma unroll
        for (int kc = 0; kc < 4; kc++) {
            const uint32_t a0 = pa0[2 * kc],     a1 = pa1[2 * kc];
            const uint32_t a2 = pa0[2 * kc + 1], a3 = pa1[2 * kc + 1];
            const uint32_t* v0 = &Vsi[(8 * kc + t4) * 72];
            const uint32_t* v1 = &Vsi[(8 * kc + t4 + 4) * 72];
#pragma unroll
            for (int jn = 0; jn < 8; jn++) {
                mma_f16(o[jn], a0, a1, a2, a3, v0[8 * jn + g], v1[8 * jn + g]);
            }
        }
    }

    // ---- epilogue ----
    const size_t pidx = (size_t)((b * NT + qt) * MAXSPL + split);
    float* op = g_opart + pidx * (BQ * HH);
#pragma unroll
    for (int jn = 0; jn < 8; jn++) {
        const int n = 8 * jn + 2 * t4;
        *(float2*)(op + (size_t)(r0 + g) * HH + n)     = make_float2(o[jn][0], o[jn][1]);
        *(float2*)(op + (size_t)(r0 + g + 8) * HH + n) = make_float2(o[jn][2], o[jn][3]);
    }
    if (t4 == 0) {
        g_mpart[pidx * BQ + r0 + g]     = m0;
        g_mpart[pidx * BQ + r0 + g + 8] = m1;
        g_lpart[pidx * BQ + r0 + g]     = l0;
        g_lpart[pidx * BQ + r0 + g + 8] = l1;
    }
}

// ===========================================================================
// Merge: combine <= MAXSPL partials per row (BQ=128 indexing).
// ===========================================================================
__global__ __launch_bounds__(256) void merge_kernel(float* __restrict__ out)
{
    const int gid = blockIdx.x * 256 + threadIdx.x;
    const int row = gid >> 4;
    const int cx  = (gid & 15) * 4;
    const int b  = row >> 12;
    const int t  = row & (TT - 1);
    const int qt = t >> 7;
    const int r  = t & (BQ - 1);
    const int ns = (2 * (qt + 1) + CHUNK - 1) / CHUNK;

    const size_t mlBase = (size_t)(b * NT + qt) * MAXSPL * BQ + r;

    float M = -3.0e38f;
    for (int s = 0; s < ns; s++)
        M = fmaxf(M, g_mpart[mlBase + (size_t)s * BQ]);

    float L = 0.0f;
    float a0 = 0.0f, a1 = 0.0f, a2 = 0.0f, a3 = 0.0f;
    for (int s = 0; s < ns; s++) {
        const float wgt = __expf(g_mpart[mlBase + (size_t)s * BQ] - M);
        L += wgt * g_lpart[mlBase + (size_t)s * BQ];
        const float* op = g_opart
            + (size_t)((b * NT + qt) * MAXSPL + s) * (BQ * HH) + r * HH + cx;
        float4 v = *(const float4*)op;
        a0 = fmaf(wgt, v.x, a0);
        a1 = fmaf(wgt, v.y, a1);
        a2 = fmaf(wgt, v.z, a2);
        a3 = fmaf(wgt, v.w, a3);
    }
    const float inv = 1.0f / L;
    *(float4*)(out + (size_t)row * HH + cx) =
        make_float4(a0 * inv, a1 * inv, a2 * inv, a3 * inv);
}

// ===========================================================================
extern "C" void kernel_launch(void* const* d_in, const int* in_sizes, int n_in,
                              void* d_out, int out_size)
{
    const float* x  = (const float*)d_in[0];
    const float* Wk = (const float*)d_in[1];
    const float* Wq = (const float*)d_in[2];
    const float* Wv = (const float*)d_in[3];
    float* out = (float*)d_out;

    prep_w_kernel<<<192, 256>>>(Wk, Wq, Wv);
    proj_mma_kernel<<<(BB * TT) / 64, 384>>>(x);

    dim3 gAttn(NT, MAXSPL, BB);
    attn_mma_kernel<<<gAttn, 256>>>();

    merge_kernel<<<(BB * TT * 16) / 256, 256>>>(out);
}